// round 14
// baseline (speedup 1.0000x reference)
#include <cuda_runtime.h>
#include <math.h>

#define S 48
#define BATCH 16
#define HID 512
#define NL 16
#define M_ROWS 768
#define VOUT 32000

// ---------------- device scratch ----------------
__device__ __align__(128) float g_act0[M_ROWS * HID];
__device__ __align__(128) float g_act1[M_ROWS * HID];
__device__ __align__(128) float g_G[M_ROWS * 2048];
__device__ __align__(128) float g_hping[8192];
__device__ __align__(128) float g_hpong[8192];
__device__ __align__(128) float g_dech0[NL * 8192];
__device__ __align__(128) float g_decc0[NL * 8192];
__device__ __align__(128) float g_dsb[17 * 393216];
__device__ __align__(128) unsigned long long g_WT[16 * 512 * 8 * 256];
// sync: enc dir d: cnt @ d*512, gen @ d*512+256 (separate lines). dec: cnt @1024, gen @1025.
__device__ unsigned g_syn[1536];

// ---------------- R3-protocol barrier (dec, 128 CTAs, nanosleep poll) ----------------
__device__ __forceinline__ void grid_barD(unsigned* cnt, unsigned* gen,
                                          unsigned tgt, unsigned nb) {
    __syncthreads();
    if (threadIdx.x == 0) {
        __threadfence();
        unsigned old = atomicAdd(cnt, 1u);
        if (old == nb - 1u) {
            atomicExch(cnt, 0u);
            __threadfence();
            atomicExch(gen, tgt);
        } else {
            while (*(volatile unsigned*)gen != tgt) { __nanosleep(32); }
        }
        __threadfence();
    }
    __syncthreads();
}

// ---------------- enc barrier: 16 arrivals, gen on its own line, pure spin ----------
__device__ __forceinline__ void grid_barE(unsigned* cnt, unsigned* gen, unsigned tgt) {
    __syncthreads();
    if (threadIdx.x == 0) {
        __threadfence();
        unsigned old = atomicAdd(cnt, 1u);
        if (old == 15u) {
            atomicExch(cnt, 0u);
            __threadfence();
            atomicExch(gen, tgt);
        } else {
            int sp = 0;
            while (*(volatile unsigned*)gen != tgt) {
                if (++sp > 4096) { __nanosleep(64); }   // safety only
            }
        }
        __threadfence();
    }
    __syncthreads();
}

// ---------------- embedding gather ----------------
__global__ void embed_k(const float* __restrict__ emb, const int* __restrict__ ids,
                        float* __restrict__ out) {
    int tb = blockIdx.x;
    int t = tb >> 4, b = tb & 15;
    int id = ids[b * S + t];
    const float4* src = reinterpret_cast<const float4*>(emb) + (size_t)id * (HID / 4);
    float4* dst = reinterpret_cast<float4*>(out) + (size_t)tb * (HID / 4);
    dst[threadIdx.x] = src[threadIdx.x];
}

// ---------------- one-time decoder weight transpose ----------
__global__ __launch_bounds__(256) void transpose_w_k(
    const float* __restrict__ Wih, const float* __restrict__ Whh,
    unsigned long long* __restrict__ WT) {
    __shared__ float sm[64 * 132];
    int bx = blockIdx.x;
    int kb = bx & 3, g = (bx >> 2) & 3, s = (bx >> 4) & 7, mat = (bx >> 7) & 1, l = bx >> 8;
    const float* src = (mat ? Whh : Wih) + (size_t)l * 2048 * 512;
    int tid = threadIdx.x;
    int k4 = tid & 31, r0 = tid >> 5;
#pragma unroll
    for (int it = 0; it < 8; ++it) {
        int rloc = r0 + it * 8;
        int rowg = g * 512 + s * 64 + rloc;
        float4 v = *reinterpret_cast<const float4*>(src + (size_t)rowg * 512 + kb * 128 + k4 * 4);
        *reinterpret_cast<float4*>(&sm[rloc * 132 + k4 * 4]) = v;
    }
    __syncthreads();
    int rl = tid & 63, kp0 = tid >> 6;
#pragma unroll
    for (int it = 0; it < 16; ++it) {
        int kpl = kp0 + it * 4;
        float lo = sm[rl * 132 + kpl * 2], hi = sm[rl * 132 + kpl * 2 + 1];
        unsigned long long v;
        asm("mov.b64 %0, {%1,%2};" : "=l"(v) : "f"(lo), "f"(hi));
        int kp = mat * 256 + kb * 64 + kpl;
        WT[(((size_t)l * 512 + kp) * 8 + s) * 256 + g * 64 + rl] = v;
    }
}

// -------- fp32 GEMM: C[m][n]=A.W^T+b, M=768,K=512 ------
__global__ __launch_bounds__(256) void gemm_k(
    const float* __restrict__ A, const float* __restrict__ W,
    const float* __restrict__ bias, float* __restrict__ C,
    size_t sB, size_t sT, size_t sN) {
    __shared__ float As[2][16 * 68];
    __shared__ float Ws[2][16 * 68];
    int tid = threadIdx.x;
    int tx = tid & 15, ty = tid >> 4;
    int n0 = blockIdx.x * 64, m0 = blockIdx.y * 64;
    int r = tid >> 2, kq = (tid & 3) * 4;

    const float* Arow = A + (size_t)(m0 + r) * 512 + kq;
    const float* Wrow = W + (size_t)(n0 + r) * 512 + kq;

    float4 a = *reinterpret_cast<const float4*>(Arow);
    float4 w = *reinterpret_cast<const float4*>(Wrow);
    As[0][(kq + 0) * 68 + r] = a.x; As[0][(kq + 1) * 68 + r] = a.y;
    As[0][(kq + 2) * 68 + r] = a.z; As[0][(kq + 3) * 68 + r] = a.w;
    Ws[0][(kq + 0) * 68 + r] = w.x; Ws[0][(kq + 1) * 68 + r] = w.y;
    Ws[0][(kq + 2) * 68 + r] = w.z; Ws[0][(kq + 3) * 68 + r] = w.w;
    __syncthreads();

    float acc[16];
#pragma unroll
    for (int i = 0; i < 16; ++i) acc[i] = 0.f;

    for (int k0 = 0; k0 < 512; k0 += 16) {
        int cur = (k0 >> 4) & 1;
        if (k0 + 16 < 512) {
            a = *reinterpret_cast<const float4*>(Arow + k0 + 16);
            w = *reinterpret_cast<const float4*>(Wrow + k0 + 16);
        }
#pragma unroll
        for (int kk = 0; kk < 16; ++kk) {
            float4 av = *reinterpret_cast<const float4*>(&As[cur][kk * 68 + ty * 4]);
            float4 wv = *reinterpret_cast<const float4*>(&Ws[cur][kk * 68 + tx * 4]);
            acc[0]  += av.x * wv.x; acc[1]  += av.x * wv.y; acc[2]  += av.x * wv.z; acc[3]  += av.x * wv.w;
            acc[4]  += av.y * wv.x; acc[5]  += av.y * wv.y; acc[6]  += av.y * wv.z; acc[7]  += av.y * wv.w;
            acc[8]  += av.z * wv.x; acc[9]  += av.z * wv.y; acc[10] += av.z * wv.z; acc[11] += av.z * wv.w;
            acc[12] += av.w * wv.x; acc[13] += av.w * wv.y; acc[14] += av.w * wv.z; acc[15] += av.w * wv.w;
        }
        if (k0 + 16 < 512) {
            int nxt = cur ^ 1;
            As[nxt][(kq + 0) * 68 + r] = a.x; As[nxt][(kq + 1) * 68 + r] = a.y;
            As[nxt][(kq + 2) * 68 + r] = a.z; As[nxt][(kq + 3) * 68 + r] = a.w;
            Ws[nxt][(kq + 0) * 68 + r] = w.x; Ws[nxt][(kq + 1) * 68 + r] = w.y;
            Ws[nxt][(kq + 2) * 68 + r] = w.z; Ws[nxt][(kq + 3) * 68 + r] = w.w;
        }
        __syncthreads();
    }
#pragma unroll
    for (int i = 0; i < 4; ++i) {
        int m = m0 + ty * 4 + i;
        int b = m & 15, t = m >> 4;
#pragma unroll
        for (int jx = 0; jx < 4; ++jx) {
            int n = n0 + tx * 4 + jx;
            C[(size_t)b * sB + (size_t)t * sT + (size_t)n * sN] = acc[i * 4 + jx] + bias[n];
        }
    }
}

// -------- projection GEMM: A rows are (b*48+t), coalesced out[b][v][t] stores ------
__global__ __launch_bounds__(256) void proj_k(
    const float* __restrict__ A, const float* __restrict__ W,
    const float* __restrict__ bias, float* __restrict__ C) {
    __shared__ float As[2][16 * 68];
    __shared__ float Ws[2][16 * 68];
    int tid = threadIdx.x;
    int tx = tid & 15, ty = tid >> 4;
    int n0 = blockIdx.x * 64, m0 = blockIdx.y * 64;
    int r = tid >> 2, kq = (tid & 3) * 4;

    const float* Arow = A + (size_t)(m0 + r) * 512 + kq;
    const float* Wrow = W + (size_t)(n0 + r) * 512 + kq;

    float4 a = *reinterpret_cast<const float4*>(Arow);
    float4 w = *reinterpret_cast<const float4*>(Wrow);
    As[0][(kq + 0) * 68 + r] = a.x; As[0][(kq + 1) * 68 + r] = a.y;
    As[0][(kq + 2) * 68 + r] = a.z; As[0][(kq + 3) * 68 + r] = a.w;
    Ws[0][(kq + 0) * 68 + r] = w.x; Ws[0][(kq + 1) * 68 + r] = w.y;
    Ws[0][(kq + 2) * 68 + r] = w.z; Ws[0][(kq + 3) * 68 + r] = w.w;
    __syncthreads();

    float acc[16];
#pragma unroll
    for (int i = 0; i < 16; ++i) acc[i] = 0.f;

    for (int k0 = 0; k0 < 512; k0 += 16) {
        int cur = (k0 >> 4) & 1;
        if (k0 + 16 < 512) {
            a = *reinterpret_cast<const float4*>(Arow + k0 + 16);
            w = *reinterpret_cast<const float4*>(Wrow + k0 + 16);
        }
#pragma unroll
        for (int kk = 0; kk < 16; ++kk) {
            float4 av = *reinterpret_cast<const float4*>(&As[cur][kk * 68 + ty * 4]);
            float4 wv = *reinterpret_cast<const float4*>(&Ws[cur][kk * 68 + tx * 4]);
            acc[0]  += av.x * wv.x; acc[1]  += av.x * wv.y; acc[2]  += av.x * wv.z; acc[3]  += av.x * wv.w;
            acc[4]  += av.y * wv.x; acc[5]  += av.y * wv.y; acc[6]  += av.y * wv.z; acc[7]  += av.y * wv.w;
            acc[8]  += av.z * wv.x; acc[9]  += av.z * wv.y; acc[10] += av.z * wv.z; acc[11] += av.z * wv.w;
            acc[12] += av.w * wv.x; acc[13] += av.w * wv.y; acc[14] += av.w * wv.z; acc[15] += av.w * wv.w;
        }
        if (k0 + 16 < 512) {
            int nxt = cur ^ 1;
            As[nxt][(kq + 0) * 68 + r] = a.x; As[nxt][(kq + 1) * 68 + r] = a.y;
            As[nxt][(kq + 2) * 68 + r] = a.z; As[nxt][(kq + 3) * 68 + r] = a.w;
            Ws[nxt][(kq + 0) * 68 + r] = w.x; Ws[nxt][(kq + 1) * 68 + r] = w.y;
            Ws[nxt][(kq + 2) * 68 + r] = w.z; Ws[nxt][(kq + 3) * 68 + r] = w.w;
        }
        __syncthreads();
    }
    float* smo = &As[0][0];
#pragma unroll
    for (int i = 0; i < 4; ++i)
#pragma unroll
        for (int jx = 0; jx < 4; ++jx)
            smo[(ty * 4 + i) * 68 + tx * 4 + jx] = acc[i * 4 + jx] + bias[n0 + tx * 4 + jx];
    __syncthreads();
#pragma unroll
    for (int it = 0; it < 16; ++it) {
        int idx = tid + it * 256;
        int m = idx & 63, n = idx >> 6;
        int mg = m0 + m;
        int b = mg / 48, t = mg - b * 48;
        C[(size_t)b * ((size_t)VOUT * 48) + (size_t)(n0 + n) * 48 + t] = smo[m * 68 + n];
    }
}

__device__ __forceinline__ float sigm(float x) { return 1.f / (1.f + expf(-x)); }

#define FMA2(acc, wv, xv) asm("fma.rn.f32x2 %0, %1, %2, %0;" : "+l"(acc) : "l"(wv), "l"(xv))
#define LDG_CG_V2(lo, hi, ptr) \
    asm("ld.global.cg.v2.u64 {%0,%1},[%2];" : "=l"(lo), "=l"(hi) : "l"(ptr))

// ======================= encoder v2: 32 CTAs x 256 thr, 16 CTAs/dir ====
// CTA: dir = bx>>4, ci = bx&15, owns j in [ci*16, ci*16+16) -> 64 gate rows.
// Thread: rl = tid&63 (row: g=rl>>4, jl=rl&15), kc = tid>>6 (k chunk of 64 = 32 k-pairs).
__global__ __launch_bounds__(256, 1) void enc_layer_k2(
    const float* __restrict__ Whh,             // (2,1024,256)
    const float* __restrict__ G, float* __restrict__ xs_out,
    float* __restrict__ hp, float* __restrict__ hq,
    float* __restrict__ dh, float* __restrict__ dc) {
    __shared__ unsigned long long hbuf[2176];  // [128 kp][17 pad] (b inner)
    __shared__ float red[4352];                // [4 kc][64 rl][17 pad-b]
    __shared__ unsigned s_base;

    int tid = threadIdx.x;
    int dir = blockIdx.x >> 4;
    int ci = blockIdx.x & 15;
    int j0 = ci * 16;
    int rl = tid & 63;
    int kc = tid >> 6;
    int g = rl >> 4, jl = rl & 15;
    int row = g * 256 + j0 + jl;

    unsigned* cnt = &g_syn[dir * 512];
    unsigned* gen = &g_syn[dir * 512 + 256];

    // weights -> k-pair ULLs in registers (held all 48 steps)
    unsigned long long wd[32];
    {
        const float4* wp = reinterpret_cast<const float4*>(
            Whh + (size_t)dir * 262144 + (size_t)row * 256 + kc * 64);
#pragma unroll
        for (int i = 0; i < 16; ++i) {
            float4 v = wp[i];
            asm("mov.b64 %0, {%1,%2};" : "=l"(wd[2 * i])     : "f"(v.x), "f"(v.y));
            asm("mov.b64 %0, {%1,%2};" : "=l"(wd[2 * i + 1]) : "f"(v.z), "f"(v.w));
        }
    }
    if (tid == 0) s_base = *(volatile unsigned*)gen;
    __syncthreads();
    unsigned base = s_base;

    // update-thread identity: uj = tid>>4 (j-local), ub = tid&15 (batch)
    int uj = tid >> 4, ub = tid & 15;
    float creg = 0.f;
    float gi, gf, gg_, go;
    {
        int tt0 = dir ? 47 : 0;
        const float* Gp = G + (size_t)(tt0 * 16 + ub) * 2048 + dir * 1024 + j0 + uj;
        gi = Gp[0]; gf = Gp[256]; gg_ = Gp[512]; go = Gp[768];
    }
    int sb = tid >> 4, si = tid & 15;          // staging roles

    for (int t = 0; t < 48; ++t) {
        int tt = dir ? (47 - t) : t;
        float* h_out = (t & 1) ? hp : hq;

        if (t > 0) {
            const float* h_in = ((t & 1) ? hq : hp) + dir * 4096;
#pragma unroll
            for (int i = 0; i < 8; ++i) {
                int kp = si + i * 16;
                hbuf[kp * 17 + sb] = *reinterpret_cast<const unsigned long long*>(
                    h_in + sb * 256 + kp * 2);
            }
            __syncthreads();

            unsigned long long acc[16];
#pragma unroll
            for (int b = 0; b < 16; ++b) acc[b] = 0ull;
#pragma unroll
            for (int i = 0; i < 32; ++i) {
                unsigned long long wv = wd[i];
                int p = (kc * 32 + i) * 17;
#pragma unroll
                for (int b = 0; b < 16; ++b) FMA2(acc[b], wv, hbuf[p + b]);
            }
#pragma unroll
            for (int b = 0; b < 16; ++b) {
                float lo, hi;
                asm("mov.b64 {%0,%1}, %2;" : "=f"(lo), "=f"(hi) : "l"(acc[b]));
                red[kc * 1088 + rl * 17 + b] = lo + hi;
            }
        } else {
#pragma unroll
            for (int b = 0; b < 16; ++b) red[kc * 1088 + rl * 17 + b] = 0.f;
        }
        __syncthreads();

        // LSTM update: all 256 threads, cell (uj, ub)
        {
            int r0 = (0 * 16 + uj) * 17 + ub;
            int r1 = (1 * 16 + uj) * 17 + ub;
            int r2 = (2 * 16 + uj) * 17 + ub;
            int r3 = (3 * 16 + uj) * 17 + ub;
            float ip = red[r0] + red[1088 + r0] + red[2176 + r0] + red[3264 + r0] + gi;
            float fp = red[r1] + red[1088 + r1] + red[2176 + r1] + red[3264 + r1] + gf;
            float gp = red[r2] + red[1088 + r2] + red[2176 + r2] + red[3264 + r2] + gg_;
            float op = red[r3] + red[1088 + r3] + red[2176 + r3] + red[3264 + r3] + go;
            float c = sigm(fp) * creg + sigm(ip) * tanhf(gp);
            creg = c;
            float h = sigm(op) * tanhf(c);
            h_out[dir * 4096 + ub * 256 + j0 + uj] = h;
            xs_out[(size_t)(tt * 16 + ub) * 512 + dir * 256 + j0 + uj] = h;
            if (t == 47) {
                dh[ub * 512 + dir * 256 + j0 + uj] = h;
                dc[ub * 512 + dir * 256 + j0 + uj] = c;
            }
        }
        if (t < 47) {
            int ttn = dir ? (47 - (t + 1)) : (t + 1);
            const float* Gp = G + (size_t)(ttn * 16 + ub) * 2048 + dir * 1024 + j0 + uj;
            gi = Gp[0]; gf = Gp[256]; gg_ = Gp[512]; go = Gp[768];
            grid_barE(cnt, gen, base + 1 + t);
        }
    }
}

// ======================= decoder wavefront (R13, unchanged) ====
__global__ __launch_bounds__(256, 1) void dec_wave_k(
    const unsigned long long* __restrict__ WT,
    const float* __restrict__ bias,
    const float* __restrict__ dh, const float* __restrict__ dc) {
    __shared__ unsigned long long xh[2176 * 2];
    __shared__ float c_sm[1024];
    __shared__ unsigned s_base;
    float* pre = reinterpret_cast<float*>(xh);

    int tid = threadIdx.x;
    int l = blockIdx.x >> 3, s = blockIdx.x & 7;
    int rp = tid & 127;
    int kh = tid >> 7;

    int g0 = (2 * rp) >> 6;
    int rl0 = (2 * rp) & 63;
    int rowg = g0 * 512 + s * 64 + rl0;
    float bv0 = bias[l * 2048 + rowg];
    float bv1 = bias[l * 2048 + rowg + 1];

    for (int i = tid; i < 1024; i += 256) {
        int jj = i >> 4, b = i & 15;
        c_sm[i] = dc[(size_t)l * 8192 + b * 512 + s * 64 + jj];
    }
    unsigned* cnt = &g_syn[1024];
    unsigned* gen = &g_syn[1025];
    if (tid == 0) s_base = *(volatile unsigned*)gen;
    __syncthreads();
    unsigned base = s_base;

    const float* dsl = g_dsb + (size_t)l * 393216;
    float* dslo = g_dsb + (size_t)(l + 1) * 393216;
    const float* h0 = dh + (size_t)l * 8192;

    int sb = tid >> 4, si = tid & 15;
    unsigned long long* xbuf = xh;
    unsigned long long* hbuf = xh + 2176;
    unsigned long long* mybuf = kh ? hbuf : xbuf;

    const unsigned long long* WTb = WT + ((size_t)l * 524288 + (size_t)s * 128 + (size_t)rp) * 2;

    for (int w = 0; w < 63; ++w) {
        int t = w - l;
        if (t >= 0 && t < 48) {
            unsigned long long acc0[16], acc1[16];
#pragma unroll
            for (int b = 0; b < 16; ++b) { acc0[b] = 0ull; acc1[b] = 0ull; }

            const float* xsrc = dsl + (size_t)t * 8192;
            const float* hsrc;
            size_t hstr;
            if (t == 0)        { hsrc = h0;                               hstr = 512;   }
            else if (l == 15)  { hsrc = dslo + (size_t)(t - 1) * 512;     hstr = 24576; }
            else               { hsrc = dslo + (size_t)(t - 1) * 8192;    hstr = 512;   }

#pragma unroll 1
            for (int half = 0; half < 2; ++half) {
                __syncthreads();
#pragma unroll
                for (int i = 0; i < 8; ++i) {
                    int kp = si + i * 16;
                    xbuf[kp * 17 + sb] = *reinterpret_cast<const unsigned long long*>(
                        xsrc + (size_t)sb * 512 + half * 256 + kp * 2);
                    hbuf[kp * 17 + sb] = *reinterpret_cast<const unsigned long long*>(
                        hsrc + (size_t)sb * hstr + half * 256 + kp * 2);
                }
                __syncthreads();

                const unsigned long long* wp = WTb + (size_t)(kh * 256 + half * 128) * 2048;
                unsigned long long wrx[8], wry[8];
#pragma unroll
                for (int i = 0; i < 8; ++i) LDG_CG_V2(wrx[i], wry[i], wp + (size_t)i * 2048);
#pragma unroll 8
                for (int kq = 0; kq < 120; ++kq) {
                    unsigned long long wa = wrx[kq & 7], wb_ = wry[kq & 7];
                    LDG_CG_V2(wrx[kq & 7], wry[kq & 7], wp + (size_t)(kq + 8) * 2048);
                    int p = kq * 17;
#pragma unroll
                    for (int b = 0; b < 16; ++b) {
                        unsigned long long xv = mybuf[p + b];
                        FMA2(acc0[b], wa, xv);
                        FMA2(acc1[b], wb_, xv);
                    }
                }
#pragma unroll
                for (int kq = 120; kq < 128; ++kq) {
                    unsigned long long wa = wrx[kq & 7], wb_ = wry[kq & 7];
                    int p = kq * 17;
#pragma unroll
                    for (int b = 0; b < 16; ++b) {
                        unsigned long long xv = mybuf[p + b];
                        FMA2(acc0[b], wa, xv);
                        FMA2(acc1[b], wb_, xv);
                    }
                }
            }
            __syncthreads();

            int pr0 = (2 * rp) * 17, pr1 = (2 * rp + 1) * 17;
            if (kh == 0) {
#pragma unroll
                for (int b = 0; b < 16; ++b) {
                    float lo, hi;
                    asm("mov.b64 {%0,%1}, %2;" : "=f"(lo), "=f"(hi) : "l"(acc0[b]));
                    pre[pr0 + b] = lo + hi;
                    asm("mov.b64 {%0,%1}, %2;" : "=f"(lo), "=f"(hi) : "l"(acc1[b]));
                    pre[pr1 + b] = lo + hi;
                }
            }
            __syncthreads();
            if (kh == 1) {
#pragma unroll
                for (int b = 0; b < 16; ++b) {
                    float lo, hi;
                    asm("mov.b64 {%0,%1}, %2;" : "=f"(lo), "=f"(hi) : "l"(acc0[b]));
                    pre[pr0 + b] += lo + hi + bv0;
                    asm("mov.b64 {%0,%1}, %2;" : "=f"(lo), "=f"(hi) : "l"(acc1[b]));
                    pre[pr1 + b] += lo + hi + bv1;
                }
            }
            __syncthreads();
#pragma unroll
            for (int q = 0; q < 4; ++q) {
                int idx = tid + q * 256;
                int jj = idx >> 4, b = idx & 15;
                float ip = pre[(jj) * 17 + b];
                float fp = pre[(64 + jj) * 17 + b];
                float gp = pre[(128 + jj) * 17 + b];
                float op = pre[(192 + jj) * 17 + b];
                float c = sigm(fp) * c_sm[idx] + sigm(ip) * tanhf(gp);
                c_sm[idx] = c;
                float h = sigm(op) * tanhf(c);
                if (l == 15)
                    dslo[(size_t)b * 24576 + (size_t)t * 512 + s * 64 + jj] = h;
                else
                    dslo[(size_t)t * 8192 + b * 512 + s * 64 + jj] = h;
            }
        }
        if (w < 62) grid_barD(cnt, gen, base + 1 + w, 128u);
    }
}

// ---------------- launch sequence ----------------
extern "C" void kernel_launch(void* const* d_in, const int* in_sizes, int n_in,
                              void* d_out, int out_size) {
    const int*   x        = (const int*)d_in[0];
    const int*   y        = (const int*)d_in[1];
    const float* enc_emb  = (const float*)d_in[2];
    const float* enc_Wih  = (const float*)d_in[3];
    const float* enc_Whh  = (const float*)d_in[4];
    const float* enc_b    = (const float*)d_in[5];
    const float* dec_emb  = (const float*)d_in[6];
    const float* dec_Wih  = (const float*)d_in[7];
    const float* dec_Whh  = (const float*)d_in[8];
    const float* dec_b    = (const float*)d_in[9];
    const float* lin_W    = (const float*)d_in[10];
    const float* lin_b    = (const float*)d_in[11];
    float* out = (float*)d_out;

    float *act0, *act1, *G, *hp, *hq, *dh, *dc, *dsb;
    unsigned long long* WT;
    cudaGetSymbolAddress((void**)&act0, g_act0);
    cudaGetSymbolAddress((void**)&act1, g_act1);
    cudaGetSymbolAddress((void**)&G,    g_G);
    cudaGetSymbolAddress((void**)&hp,   g_hping);
    cudaGetSymbolAddress((void**)&hq,   g_hpong);
    cudaGetSymbolAddress((void**)&dh,   g_dech0);
    cudaGetSymbolAddress((void**)&dc,   g_decc0);
    cudaGetSymbolAddress((void**)&dsb,  g_dsb);
    cudaGetSymbolAddress((void**)&WT,   g_WT);
    float* bufs[2] = {act0, act1};

    // ---- one-time decoder weight transpose ----
    transpose_w_k<<<4096, 256>>>(dec_Wih, dec_Whh, WT);

    // ---- encoder ----
    embed_k<<<768, 128>>>(enc_emb, x, bufs[0]);
    int p = 0;
    for (int l = 0; l < NL; ++l) {
        gemm_k<<<dim3(32, 12), 256>>>(bufs[p], enc_Wih + (size_t)l * 1024 * 1024,
                                      enc_b + l * 2048, G,
                                      (size_t)2048, (size_t)32768, (size_t)1);
        enc_layer_k2<<<32, 256>>>(enc_Whh + (size_t)l * 2 * 1024 * 256, G,
                                  bufs[1 - p], hp, hq,
                                  dh + l * 8192, dc + l * 8192);
        p ^= 1;
    }

    // ---- decoder: embed + single wavefront kernel ----
    embed_k<<<768, 128>>>(dec_emb, y, dsb);
    dec_wave_k<<<128, 256>>>(WT, dec_b, dh, dc);

    // ---- final projection (coalesced) on g_dsb[16] ----
    proj_k<<<dim3(500, 12), 256>>>(dsb + (size_t)16 * 393216, lin_W, lin_b, out);
}

// round 15
// speedup vs baseline: 1.1179x; 1.1179x over previous
#include <cuda_runtime.h>
#include <math.h>

#define S 48
#define BATCH 16
#define HID 512
#define NL 16
#define M_ROWS 768
#define VOUT 32000

// ---------------- device scratch ----------------
__device__ __align__(128) float g_act0[M_ROWS * HID];
__device__ __align__(128) float g_act1[M_ROWS * HID];
__device__ __align__(128) float g_G[M_ROWS * 2048];
__device__ __align__(128) float g_hping[8192];
__device__ __align__(128) float g_hpong[8192];
__device__ __align__(128) float g_dech0[NL * 8192];
__device__ __align__(128) float g_decc0[NL * 8192];
__device__ __align__(128) float g_dsb[17 * 393216];
__device__ __align__(128) unsigned long long g_WT[16 * 512 * 8 * 256];
// sync layout (all words on distinct 1KB lines, stride 256 u32):
// enc dir d (d=0,1): group cnts @ [d*4096 + g*256] (g<8), root @ [d*4096+2048], gen @ [d*4096+2304]
// dec: group cnts @ [8192 + g*256] (g<16), root @ [8192+4096], gen @ [8192+4352]
__device__ unsigned g_syn[16384];

// ---------------- two-level grid barrier (R3 release + nanosleep poll) ----------
__device__ __forceinline__ void gbar2(unsigned* gcnt, unsigned* rcnt, unsigned* gen,
                                      unsigned gsz, unsigned nroot, unsigned tgt) {
    __syncthreads();
    if (threadIdx.x == 0) {
        __threadfence();
        unsigned old = atomicAdd(gcnt, 1u);
        if (old == gsz - 1u) {
            atomicExch(gcnt, 0u);
            old = atomicAdd(rcnt, 1u);
            if (old == nroot - 1u) {
                atomicExch(rcnt, 0u);
                __threadfence();
                atomicExch(gen, tgt);
            }
        }
        while (*(volatile unsigned*)gen != tgt) { __nanosleep(32); }
        __threadfence();
    }
    __syncthreads();
}

// ---------------- embedding gather ----------------
__global__ void embed_k(const float* __restrict__ emb, const int* __restrict__ ids,
                        float* __restrict__ out) {
    int tb = blockIdx.x;
    int t = tb >> 4, b = tb & 15;
    int id = ids[b * S + t];
    const float4* src = reinterpret_cast<const float4*>(emb) + (size_t)id * (HID / 4);
    float4* dst = reinterpret_cast<float4*>(out) + (size_t)tb * (HID / 4);
    dst[threadIdx.x] = src[threadIdx.x];
}

// ---------------- one-time decoder weight transpose ----------
__global__ __launch_bounds__(256) void transpose_w_k(
    const float* __restrict__ Wih, const float* __restrict__ Whh,
    unsigned long long* __restrict__ WT) {
    __shared__ float sm[64 * 132];
    int bx = blockIdx.x;
    int kb = bx & 3, g = (bx >> 2) & 3, s = (bx >> 4) & 7, mat = (bx >> 7) & 1, l = bx >> 8;
    const float* src = (mat ? Whh : Wih) + (size_t)l * 2048 * 512;
    int tid = threadIdx.x;
    int k4 = tid & 31, r0 = tid >> 5;
#pragma unroll
    for (int it = 0; it < 8; ++it) {
        int rloc = r0 + it * 8;
        int rowg = g * 512 + s * 64 + rloc;
        float4 v = *reinterpret_cast<const float4*>(src + (size_t)rowg * 512 + kb * 128 + k4 * 4);
        *reinterpret_cast<float4*>(&sm[rloc * 132 + k4 * 4]) = v;
    }
    __syncthreads();
    int rl = tid & 63, kp0 = tid >> 6;
#pragma unroll
    for (int it = 0; it < 16; ++it) {
        int kpl = kp0 + it * 4;
        float lo = sm[rl * 132 + kpl * 2], hi = sm[rl * 132 + kpl * 2 + 1];
        unsigned long long v;
        asm("mov.b64 %0, {%1,%2};" : "=l"(v) : "f"(lo), "f"(hi));
        int kp = mat * 256 + kb * 64 + kpl;
        WT[(((size_t)l * 512 + kp) * 8 + s) * 256 + g * 64 + rl] = v;
    }
}

// -------- fp32 GEMM: C[m][n]=A.W^T+b, M=768,K=512 ------
__global__ __launch_bounds__(256) void gemm_k(
    const float* __restrict__ A, const float* __restrict__ W,
    const float* __restrict__ bias, float* __restrict__ C,
    size_t sB, size_t sT, size_t sN) {
    __shared__ float As[2][16 * 68];
    __shared__ float Ws[2][16 * 68];
    int tid = threadIdx.x;
    int tx = tid & 15, ty = tid >> 4;
    int n0 = blockIdx.x * 64, m0 = blockIdx.y * 64;
    int r = tid >> 2, kq = (tid & 3) * 4;

    const float* Arow = A + (size_t)(m0 + r) * 512 + kq;
    const float* Wrow = W + (size_t)(n0 + r) * 512 + kq;

    float4 a = *reinterpret_cast<const float4*>(Arow);
    float4 w = *reinterpret_cast<const float4*>(Wrow);
    As[0][(kq + 0) * 68 + r] = a.x; As[0][(kq + 1) * 68 + r] = a.y;
    As[0][(kq + 2) * 68 + r] = a.z; As[0][(kq + 3) * 68 + r] = a.w;
    Ws[0][(kq + 0) * 68 + r] = w.x; Ws[0][(kq + 1) * 68 + r] = w.y;
    Ws[0][(kq + 2) * 68 + r] = w.z; Ws[0][(kq + 3) * 68 + r] = w.w;
    __syncthreads();

    float acc[16];
#pragma unroll
    for (int i = 0; i < 16; ++i) acc[i] = 0.f;

    for (int k0 = 0; k0 < 512; k0 += 16) {
        int cur = (k0 >> 4) & 1;
        if (k0 + 16 < 512) {
            a = *reinterpret_cast<const float4*>(Arow + k0 + 16);
            w = *reinterpret_cast<const float4*>(Wrow + k0 + 16);
        }
#pragma unroll
        for (int kk = 0; kk < 16; ++kk) {
            float4 av = *reinterpret_cast<const float4*>(&As[cur][kk * 68 + ty * 4]);
            float4 wv = *reinterpret_cast<const float4*>(&Ws[cur][kk * 68 + tx * 4]);
            acc[0]  += av.x * wv.x; acc[1]  += av.x * wv.y; acc[2]  += av.x * wv.z; acc[3]  += av.x * wv.w;
            acc[4]  += av.y * wv.x; acc[5]  += av.y * wv.y; acc[6]  += av.y * wv.z; acc[7]  += av.y * wv.w;
            acc[8]  += av.z * wv.x; acc[9]  += av.z * wv.y; acc[10] += av.z * wv.z; acc[11] += av.z * wv.w;
            acc[12] += av.w * wv.x; acc[13] += av.w * wv.y; acc[14] += av.w * wv.z; acc[15] += av.w * wv.w;
        }
        if (k0 + 16 < 512) {
            int nxt = cur ^ 1;
            As[nxt][(kq + 0) * 68 + r] = a.x; As[nxt][(kq + 1) * 68 + r] = a.y;
            As[nxt][(kq + 2) * 68 + r] = a.z; As[nxt][(kq + 3) * 68 + r] = a.w;
            Ws[nxt][(kq + 0) * 68 + r] = w.x; Ws[nxt][(kq + 1) * 68 + r] = w.y;
            Ws[nxt][(kq + 2) * 68 + r] = w.z; Ws[nxt][(kq + 3) * 68 + r] = w.w;
        }
        __syncthreads();
    }
#pragma unroll
    for (int i = 0; i < 4; ++i) {
        int m = m0 + ty * 4 + i;
        int b = m & 15, t = m >> 4;
#pragma unroll
        for (int jx = 0; jx < 4; ++jx) {
            int n = n0 + tx * 4 + jx;
            C[(size_t)b * sB + (size_t)t * sT + (size_t)n * sN] = acc[i * 4 + jx] + bias[n];
        }
    }
}

// -------- projection GEMM: A rows are (b*48+t), coalesced out[b][v][t] stores ------
__global__ __launch_bounds__(256) void proj_k(
    const float* __restrict__ A, const float* __restrict__ W,
    const float* __restrict__ bias, float* __restrict__ C) {
    __shared__ float As[2][16 * 68];
    __shared__ float Ws[2][16 * 68];
    int tid = threadIdx.x;
    int tx = tid & 15, ty = tid >> 4;
    int n0 = blockIdx.x * 64, m0 = blockIdx.y * 64;
    int r = tid >> 2, kq = (tid & 3) * 4;

    const float* Arow = A + (size_t)(m0 + r) * 512 + kq;
    const float* Wrow = W + (size_t)(n0 + r) * 512 + kq;

    float4 a = *reinterpret_cast<const float4*>(Arow);
    float4 w = *reinterpret_cast<const float4*>(Wrow);
    As[0][(kq + 0) * 68 + r] = a.x; As[0][(kq + 1) * 68 + r] = a.y;
    As[0][(kq + 2) * 68 + r] = a.z; As[0][(kq + 3) * 68 + r] = a.w;
    Ws[0][(kq + 0) * 68 + r] = w.x; Ws[0][(kq + 1) * 68 + r] = w.y;
    Ws[0][(kq + 2) * 68 + r] = w.z; Ws[0][(kq + 3) * 68 + r] = w.w;
    __syncthreads();

    float acc[16];
#pragma unroll
    for (int i = 0; i < 16; ++i) acc[i] = 0.f;

    for (int k0 = 0; k0 < 512; k0 += 16) {
        int cur = (k0 >> 4) & 1;
        if (k0 + 16 < 512) {
            a = *reinterpret_cast<const float4*>(Arow + k0 + 16);
            w = *reinterpret_cast<const float4*>(Wrow + k0 + 16);
        }
#pragma unroll
        for (int kk = 0; kk < 16; ++kk) {
            float4 av = *reinterpret_cast<const float4*>(&As[cur][kk * 68 + ty * 4]);
            float4 wv = *reinterpret_cast<const float4*>(&Ws[cur][kk * 68 + tx * 4]);
            acc[0]  += av.x * wv.x; acc[1]  += av.x * wv.y; acc[2]  += av.x * wv.z; acc[3]  += av.x * wv.w;
            acc[4]  += av.y * wv.x; acc[5]  += av.y * wv.y; acc[6]  += av.y * wv.z; acc[7]  += av.y * wv.w;
            acc[8]  += av.z * wv.x; acc[9]  += av.z * wv.y; acc[10] += av.z * wv.z; acc[11] += av.z * wv.w;
            acc[12] += av.w * wv.x; acc[13] += av.w * wv.y; acc[14] += av.w * wv.z; acc[15] += av.w * wv.w;
        }
        if (k0 + 16 < 512) {
            int nxt = cur ^ 1;
            As[nxt][(kq + 0) * 68 + r] = a.x; As[nxt][(kq + 1) * 68 + r] = a.y;
            As[nxt][(kq + 2) * 68 + r] = a.z; As[nxt][(kq + 3) * 68 + r] = a.w;
            Ws[nxt][(kq + 0) * 68 + r] = w.x; Ws[nxt][(kq + 1) * 68 + r] = w.y;
            Ws[nxt][(kq + 2) * 68 + r] = w.z; Ws[nxt][(kq + 3) * 68 + r] = w.w;
        }
        __syncthreads();
    }
    float* smo = &As[0][0];
#pragma unroll
    for (int i = 0; i < 4; ++i)
#pragma unroll
        for (int jx = 0; jx < 4; ++jx)
            smo[(ty * 4 + i) * 68 + tx * 4 + jx] = acc[i * 4 + jx] + bias[n0 + tx * 4 + jx];
    __syncthreads();
#pragma unroll
    for (int it = 0; it < 16; ++it) {
        int idx = tid + it * 256;
        int m = idx & 63, n = idx >> 6;
        int mg = m0 + m;
        int b = mg / 48, t = mg - b * 48;
        C[(size_t)b * ((size_t)VOUT * 48) + (size_t)(n0 + n) * 48 + t] = smo[m * 68 + n];
    }
}

__device__ __forceinline__ float sigm(float x) { return 1.f / (1.f + expf(-x)); }

#define FMA2(acc, wv, xv) asm("fma.rn.f32x2 %0, %1, %2, %0;" : "+l"(acc) : "l"(wv), "l"(xv))
#define LDG_CG_V2(lo, hi, ptr) \
    asm("ld.global.cg.v2.u64 {%0,%1},[%2];" : "=l"(lo), "=l"(hi) : "l"(ptr))

// ======================= persistent encoder layer (R13 body, 2-level bar) ====
__global__ __launch_bounds__(128, 1) void enc_layer_k(
    const float* __restrict__ Whh,             // (2,1024,256)
    const float* __restrict__ G, float* __restrict__ xs_out,
    float* __restrict__ hp, float* __restrict__ hq,
    float* __restrict__ dh, float* __restrict__ dc) {
    __shared__ float4 sm4[2112];
    __shared__ float redout[256];
    __shared__ float c_sm[64];
    __shared__ unsigned s_base;
    float* sm = (float*)sm4;
    int tid = threadIdx.x;
    int ty = tid >> 5, kc = tid & 31;
    int dir = blockIdx.x >> 6;
    int jb = blockIdx.x & 63;
    int j0 = jb * 4;
    int j = j0 + ty;

    unsigned* gcnt = &g_syn[dir * 4096 + (jb >> 3) * 256];
    unsigned* rcnt = &g_syn[dir * 4096 + 2048];
    unsigned* gen  = &g_syn[dir * 4096 + 2304];

    const float4* w4 = reinterpret_cast<const float4*>(Whh + (size_t)dir * 1024 * 256);
    float4 wr[2][4];
#pragma unroll
    for (int it = 0; it < 2; ++it) {
        int k4 = it * 32 + kc;
        wr[it][0] = w4[(size_t)(0 * 256 + j) * 64 + k4];
        wr[it][1] = w4[(size_t)(1 * 256 + j) * 64 + k4];
        wr[it][2] = w4[(size_t)(2 * 256 + j) * 64 + k4];
        wr[it][3] = w4[(size_t)(3 * 256 + j) * 64 + k4];
    }
    if (tid < 64) c_sm[tid] = 0.f;
    if (tid == 0) s_base = *(volatile unsigned*)gen;
    __syncthreads();
    unsigned base = s_base;

    int ujj = tid >> 4, ub = tid & 15;
    int ujg = j0 + ujj;
    float gi = 0.f, gf = 0.f, gg_ = 0.f, go = 0.f;
    if (tid < 64) {
        int tt0 = dir ? 47 : 0;
        const float* Gp = G + (size_t)(tt0 * 16 + ub) * 2048 + dir * 1024 + ujg;
        gi = Gp[0]; gf = Gp[256]; gg_ = Gp[512]; go = Gp[768];
    }

    for (int t = 0; t < 48; ++t) {
        int tt = dir ? (47 - t) : t;
        float* h_out = (t & 1) ? hp : hq;

        if (t > 0) {
            const float* h_in = (t & 1) ? hq : hp;
            const float4* hin4 = reinterpret_cast<const float4*>(h_in + dir * 4096);
#pragma unroll
            for (int i = 0; i < 8; ++i) sm4[tid + i * 128] = hin4[tid + i * 128];
            __syncthreads();

            float acc[64];
#pragma unroll
            for (int i = 0; i < 64; ++i) acc[i] = 0.f;
#pragma unroll
            for (int it = 0; it < 2; ++it) {
                int k4 = it * 32 + kc;
#pragma unroll
                for (int b = 0; b < 16; ++b) {
                    float4 hv = sm4[b * 64 + k4];
                    acc[0 * 16 + b] += wr[it][0].x * hv.x + wr[it][0].y * hv.y + wr[it][0].z * hv.z + wr[it][0].w * hv.w;
                    acc[1 * 16 + b] += wr[it][1].x * hv.x + wr[it][1].y * hv.y + wr[it][1].z * hv.z + wr[it][1].w * hv.w;
                    acc[2 * 16 + b] += wr[it][2].x * hv.x + wr[it][2].y * hv.y + wr[it][2].z * hv.z + wr[it][2].w * hv.w;
                    acc[3 * 16 + b] += wr[it][3].x * hv.x + wr[it][3].y * hv.y + wr[it][3].z * hv.z + wr[it][3].w * hv.w;
                }
            }
            __syncthreads();
#pragma unroll
            for (int gg = 0; gg < 4; ++gg)
#pragma unroll
                for (int b = 0; b < 16; ++b)
                    sm[((ty * 4 + gg) * 16 + b) * 33 + kc] = acc[gg * 16 + b];
            __syncthreads();
#pragma unroll
            for (int rr = 0; rr < 2; ++rr) {
                int o = tid + rr * 128;
                float ss = 0.f;
#pragma unroll
                for (int q = 0; q < 32; ++q) ss += sm[o * 33 + q];
                redout[o] = ss;
            }
        } else {
#pragma unroll
            for (int rr = 0; rr < 2; ++rr) redout[tid + rr * 128] = 0.f;
        }
        __syncthreads();

        if (tid < 64) {
            float ip = redout[(ujj * 4 + 0) * 16 + ub] + gi;
            float fp = redout[(ujj * 4 + 1) * 16 + ub] + gf;
            float gp = redout[(ujj * 4 + 2) * 16 + ub] + gg_;
            float op = redout[(ujj * 4 + 3) * 16 + ub] + go;
            float c = sigm(fp) * c_sm[tid] + sigm(ip) * tanhf(gp);
            c_sm[tid] = c;
            float h = sigm(op) * tanhf(c);
            h_out[dir * 4096 + ub * 256 + ujg] = h;
            xs_out[(size_t)(tt * 16 + ub) * 512 + dir * 256 + ujg] = h;
            if (t == 47) {
                dh[ub * 512 + dir * 256 + ujg] = h;
                dc[ub * 512 + dir * 256 + ujg] = c;
            }
        }
        if (t < 47) {
            if (tid < 64) {
                int ttn = dir ? (47 - (t + 1)) : (t + 1);
                const float* Gp = G + (size_t)(ttn * 16 + ub) * 2048 + dir * 1024 + ujg;
                gi = Gp[0]; gf = Gp[256]; gg_ = Gp[512]; go = Gp[768];
            }
            gbar2(gcnt, rcnt, gen, 8u, 8u, base + 1 + t);
        }
    }
}

// ======================= decoder wavefront (R13 body, 2-level bar) ====
__global__ __launch_bounds__(256, 1) void dec_wave_k(
    const unsigned long long* __restrict__ WT,
    const float* __restrict__ bias,
    const float* __restrict__ dh, const float* __restrict__ dc) {
    __shared__ unsigned long long xh[2176 * 2];
    __shared__ float c_sm[1024];
    __shared__ unsigned s_base;
    float* pre = reinterpret_cast<float*>(xh);

    int tid = threadIdx.x;
    int l = blockIdx.x >> 3, s = blockIdx.x & 7;
    int rp = tid & 127;
    int kh = tid >> 7;

    int g0 = (2 * rp) >> 6;
    int rl0 = (2 * rp) & 63;
    int rowg = g0 * 512 + s * 64 + rl0;
    float bv0 = bias[l * 2048 + rowg];
    float bv1 = bias[l * 2048 + rowg + 1];

    for (int i = tid; i < 1024; i += 256) {
        int jj = i >> 4, b = i & 15;
        c_sm[i] = dc[(size_t)l * 8192 + b * 512 + s * 64 + jj];
    }
    unsigned* gcnt = &g_syn[8192 + (blockIdx.x >> 3) * 256];
    unsigned* rcnt = &g_syn[8192 + 4096];
    unsigned* gen  = &g_syn[8192 + 4352];
    if (tid == 0) s_base = *(volatile unsigned*)gen;
    __syncthreads();
    unsigned base = s_base;

    const float* dsl = g_dsb + (size_t)l * 393216;
    float* dslo = g_dsb + (size_t)(l + 1) * 393216;
    const float* h0 = dh + (size_t)l * 8192;

    int sb = tid >> 4, si = tid & 15;
    unsigned long long* xbuf = xh;
    unsigned long long* hbuf = xh + 2176;
    unsigned long long* mybuf = kh ? hbuf : xbuf;

    const unsigned long long* WTb = WT + ((size_t)l * 524288 + (size_t)s * 128 + (size_t)rp) * 2;

    for (int w = 0; w < 63; ++w) {
        int t = w - l;
        if (t >= 0 && t < 48) {
            unsigned long long acc0[16], acc1[16];
#pragma unroll
            for (int b = 0; b < 16; ++b) { acc0[b] = 0ull; acc1[b] = 0ull; }

            const float* xsrc = dsl + (size_t)t * 8192;
            const float* hsrc;
            size_t hstr;
            if (t == 0)        { hsrc = h0;                               hstr = 512;   }
            else if (l == 15)  { hsrc = dslo + (size_t)(t - 1) * 512;     hstr = 24576; }
            else               { hsrc = dslo + (size_t)(t - 1) * 8192;    hstr = 512;   }

#pragma unroll 1
            for (int half = 0; half < 2; ++half) {
                __syncthreads();
#pragma unroll
                for (int i = 0; i < 8; ++i) {
                    int kp = si + i * 16;
                    xbuf[kp * 17 + sb] = *reinterpret_cast<const unsigned long long*>(
                        xsrc + (size_t)sb * 512 + half * 256 + kp * 2);
                    hbuf[kp * 17 + sb] = *reinterpret_cast<const unsigned long long*>(
                        hsrc + (size_t)sb * hstr + half * 256 + kp * 2);
                }
                __syncthreads();

                const unsigned long long* wp = WTb + (size_t)(kh * 256 + half * 128) * 2048;
                unsigned long long wrx[8], wry[8];
#pragma unroll
                for (int i = 0; i < 8; ++i) LDG_CG_V2(wrx[i], wry[i], wp + (size_t)i * 2048);
#pragma unroll 8
                for (int kq = 0; kq < 120; ++kq) {
                    unsigned long long wa = wrx[kq & 7], wb_ = wry[kq & 7];
                    LDG_CG_V2(wrx[kq & 7], wry[kq & 7], wp + (size_t)(kq + 8) * 2048);
                    int p = kq * 17;
#pragma unroll
                    for (int b = 0; b < 16; ++b) {
                        unsigned long long xv = mybuf[p + b];
                        FMA2(acc0[b], wa, xv);
                        FMA2(acc1[b], wb_, xv);
                    }
                }
#pragma unroll
                for (int kq = 120; kq < 128; ++kq) {
                    unsigned long long wa = wrx[kq & 7], wb_ = wry[kq & 7];
                    int p = kq * 17;
#pragma unroll
                    for (int b = 0; b < 16; ++b) {
                        unsigned long long xv = mybuf[p + b];
                        FMA2(acc0[b], wa, xv);
                        FMA2(acc1[b], wb_, xv);
                    }
                }
            }
            __syncthreads();

            int pr0 = (2 * rp) * 17, pr1 = (2 * rp + 1) * 17;
            if (kh == 0) {
#pragma unroll
                for (int b = 0; b < 16; ++b) {
                    float lo, hi;
                    asm("mov.b64 {%0,%1}, %2;" : "=f"(lo), "=f"(hi) : "l"(acc0[b]));
                    pre[pr0 + b] = lo + hi;
                    asm("mov.b64 {%0,%1}, %2;" : "=f"(lo), "=f"(hi) : "l"(acc1[b]));
                    pre[pr1 + b] = lo + hi;
                }
            }
            __syncthreads();
            if (kh == 1) {
#pragma unroll
                for (int b = 0; b < 16; ++b) {
                    float lo, hi;
                    asm("mov.b64 {%0,%1}, %2;" : "=f"(lo), "=f"(hi) : "l"(acc0[b]));
                    pre[pr0 + b] += lo + hi + bv0;
                    asm("mov.b64 {%0,%1}, %2;" : "=f"(lo), "=f"(hi) : "l"(acc1[b]));
                    pre[pr1 + b] += lo + hi + bv1;
                }
            }
            __syncthreads();
#pragma unroll
            for (int q = 0; q < 4; ++q) {
                int idx = tid + q * 256;
                int jj = idx >> 4, b = idx & 15;
                float ip = pre[(jj) * 17 + b];
                float fp = pre[(64 + jj) * 17 + b];
                float gp = pre[(128 + jj) * 17 + b];
                float op = pre[(192 + jj) * 17 + b];
                float c = sigm(fp) * c_sm[idx] + sigm(ip) * tanhf(gp);
                c_sm[idx] = c;
                float h = sigm(op) * tanhf(c);
                if (l == 15)
                    dslo[(size_t)b * 24576 + (size_t)t * 512 + s * 64 + jj] = h;
                else
                    dslo[(size_t)t * 8192 + b * 512 + s * 64 + jj] = h;
            }
        }
        if (w < 62) gbar2(gcnt, rcnt, gen, 8u, 16u, base + 1 + w);
    }
}

// ---------------- launch sequence ----------------
extern "C" void kernel_launch(void* const* d_in, const int* in_sizes, int n_in,
                              void* d_out, int out_size) {
    const int*   x        = (const int*)d_in[0];
    const int*   y        = (const int*)d_in[1];
    const float* enc_emb  = (const float*)d_in[2];
    const float* enc_Wih  = (const float*)d_in[3];
    const float* enc_Whh  = (const float*)d_in[4];
    const float* enc_b    = (const float*)d_in[5];
    const float* dec_emb  = (const float*)d_in[6];
    const float* dec_Wih  = (const float*)d_in[7];
    const float* dec_Whh  = (const float*)d_in[8];
    const float* dec_b    = (const float*)d_in[9];
    const float* lin_W    = (const float*)d_in[10];
    const float* lin_b    = (const float*)d_in[11];
    float* out = (float*)d_out;

    float *act0, *act1, *G, *hp, *hq, *dh, *dc, *dsb;
    unsigned long long* WT;
    cudaGetSymbolAddress((void**)&act0, g_act0);
    cudaGetSymbolAddress((void**)&act1, g_act1);
    cudaGetSymbolAddress((void**)&G,    g_G);
    cudaGetSymbolAddress((void**)&hp,   g_hping);
    cudaGetSymbolAddress((void**)&hq,   g_hpong);
    cudaGetSymbolAddress((void**)&dh,   g_dech0);
    cudaGetSymbolAddress((void**)&dc,   g_decc0);
    cudaGetSymbolAddress((void**)&dsb,  g_dsb);
    cudaGetSymbolAddress((void**)&WT,   g_WT);
    float* bufs[2] = {act0, act1};

    // ---- one-time decoder weight transpose ----
    transpose_w_k<<<4096, 256>>>(dec_Wih, dec_Whh, WT);

    // ---- encoder ----
    embed_k<<<768, 128>>>(enc_emb, x, bufs[0]);
    int p = 0;
    for (int l = 0; l < NL; ++l) {
        gemm_k<<<dim3(32, 12), 256>>>(bufs[p], enc_Wih + (size_t)l * 1024 * 1024,
                                      enc_b + l * 2048, G,
                                      (size_t)2048, (size_t)32768, (size_t)1);
        enc_layer_k<<<128, 128>>>(enc_Whh + (size_t)l * 2 * 1024 * 256, G,
                                  bufs[1 - p], hp, hq,
                                  dh + l * 8192, dc + l * 8192);
        p ^= 1;
    }

    // ---- decoder: embed + single wavefront kernel ----
    embed_k<<<768, 128>>>(dec_emb, y, dsb);
    dec_wave_k<<<128, 256>>>(WT, dec_b, dh, dc);

    // ---- final projection (coalesced) on g_dsb[16] ----
    proj_k<<<dim3(500, 12), 256>>>(dsb + (size_t)16 * 393216, lin_W, lin_b, out);
}